// round 6
// baseline (speedup 1.0000x reference)
#include <cuda_runtime.h>
#include <cuda_fp16.h>
#include <cstdint>

// ============================================================================
// QuantLinear: out[M,N] = x[M,K] @ dequant(qweight, scales, qzeros)[K,N]
// M=8192, K=4096, N=11008, groupsize=128, 4-bit.
//
// compute_103 PTX target => no tcgen05; tensor path = mma.sync HMMA, rt=8
// (measured R4/R5) -> GEMM floor 1.21ms. Empirical law: 16 warps/SM in TWO
// CTAs is the best latency-hiding config (R2). This round: R2 geometry +
// fragment double-buffer inside a hard 128-reg budget + fused prep.
//
// Pass 1: fused prep: x fp32 -> g_X fp16 [M,K]; dequant -> g_W fp16 [N,K].
// Pass 2: GEMM: CTA 128x128x64, 256 thr, 8 warps of 64x32, 3-stage cp.async,
//         SW128 smem, ks-level A+B fragment double-buffer.
// ============================================================================

constexpr int M = 8192;
constexpr int N = 11008;
constexpr int K = 4096;

constexpr int BM = 128;
constexpr int BN = 128;
constexpr int KC = 64;             // halves per stage = 128B rows (SW128)
constexpr int STAGES = 3;
constexpr int NK = K / KC;         // 64
constexpr int THREADS = 256;

constexpr int A_BYTES = BM * 128;                 // 16384
constexpr int STAGE_BYTES = 2 * A_BYTES;          // 32768 (A then B)
constexpr int SMEM_BYTES = STAGES * STAGE_BYTES;  // 98304 -> 2 CTAs/SM

constexpr int XWORK = M * K / 4;        // float4 items in convert part
constexpr int WWORK = (K / 8) * N;      // int32 items in dequant part

static_assert(M % BM == 0 && N % BN == 0 && K % KC == 0, "exact tiling");

__device__ __half g_X[(size_t)M * K];   // [M, K] fp16
__device__ __half g_W[(size_t)N * K];   // [N, K] fp16 (W^T), K-major

// ----------------------------------------------------------------------------
// helpers
// ----------------------------------------------------------------------------
__device__ __forceinline__ void cp16(uint32_t smem_dst, const void* gsrc) {
    asm volatile("cp.async.cg.shared.global [%0], [%1], 16;"
                 :: "r"(smem_dst), "l"(gsrc));
}

__device__ __forceinline__ void ldsm4(uint32_t* r, uint32_t addr) {
    asm volatile("ldmatrix.sync.aligned.m8n8.x4.shared.b16 {%0,%1,%2,%3}, [%4];"
                 : "=r"(r[0]), "=r"(r[1]), "=r"(r[2]), "=r"(r[3]) : "r"(addr));
}

__device__ __forceinline__ void mma16816(float* c, const uint32_t* a, const uint32_t* b) {
    asm volatile(
        "mma.sync.aligned.m16n8k16.row.col.f32.f16.f16.f32 "
        "{%0,%1,%2,%3}, {%4,%5,%6,%7}, {%8,%9}, {%0,%1,%2,%3};"
        : "+f"(c[0]), "+f"(c[1]), "+f"(c[2]), "+f"(c[3])
        : "r"(a[0]), "r"(a[1]), "r"(a[2]), "r"(a[3]), "r"(b[0]), "r"(b[1]));
}

// ----------------------------------------------------------------------------
// Pass 1: fused x-convert + dequant
// ----------------------------------------------------------------------------
__global__ void __launch_bounds__(256)
prep_kernel(const float* __restrict__ x, const int* __restrict__ qweight,
            const float* __restrict__ scales, const int* __restrict__ qzeros) {
    int idx = blockIdx.x * 256 + threadIdx.x;
    if (idx < XWORK) {
        float4 v = ((const float4*)x)[idx];
        __half2 h0 = __floats2half2_rn(v.x, v.y);
        __half2 h1 = __floats2half2_rn(v.z, v.w);
        uint2 o;
        o.x = *(unsigned*)&h0;
        o.y = *(unsigned*)&h1;
        ((uint2*)g_X)[idx] = o;
        return;
    }
    int widx = idx - XWORK;          // over (K/8)*N
    if (widx >= WWORK) return;
    int n = widx % N;
    int r = widx / N;
    int g = r >> 4;                  // groupsize 128 = 16 qweight rows
    unsigned q  = ((const unsigned*)qweight)[widx];
    unsigned qz = ((const unsigned*)qzeros)[g * (N / 8) + (n >> 3)];
    float z = (float)((qz >> ((n & 7) * 4)) & 0xF);
    float s = scales[g * N + n];
    __half2 outv[4];
#pragma unroll
    for (int j = 0; j < 4; j++) {
        float v0 = s * ((float)((q >> (8 * j))     & 0xF) - z);
        float v1 = s * ((float)((q >> (8 * j + 4)) & 0xF) - z);
        outv[j] = __floats2half2_rn(v0, v1);
    }
    *(uint4*)&g_W[(size_t)n * K + r * 8] = *(uint4*)outv;
}

// ----------------------------------------------------------------------------
// Stage loader (256 threads): A 128 rows + B 128 rows, 128B/row, SW128.
// Row r, 16B chunk c at r*128 + ((c ^ (r&7))*16).
// ----------------------------------------------------------------------------
__device__ __forceinline__ void load_stage(uint32_t sbase, int slot, int kt,
                                           const __half* Ag, const __half* Bg,
                                           int tid) {
    const uint32_t a_s = sbase + slot * STAGE_BYTES;
    const uint32_t b_s = a_s + A_BYTES;
    const __half* Ak = Ag + kt * KC;
    const __half* Bk = Bg + kt * KC;
#pragma unroll
    for (int it = 0; it < 4; it++) {        // 128 rows * 8 chunks / 256 thr
        int idx = tid + it * THREADS;
        int r = idx >> 3, c = idx & 7;
        uint32_t off = (uint32_t)r * 128 + (uint32_t)((c ^ (r & 7)) * 16);
        cp16(a_s + off, Ak + (size_t)r * K + c * 8);
        cp16(b_s + off, Bk + (size_t)r * K + c * 8);
    }
}

// ----------------------------------------------------------------------------
// Pass 2: GEMM
// ----------------------------------------------------------------------------
__global__ void __launch_bounds__(THREADS, 2)
gemm_kernel(float* __restrict__ out) {
    extern __shared__ char smem[];
    const uint32_t sbase = (uint32_t)__cvta_generic_to_shared(smem);
    const int tid  = threadIdx.x;
    const int warp = tid >> 5;
    const int lane = tid & 31;
    const int wm = warp & 1;          // 2 warps over 128 M (64 each)
    const int wn = warp >> 1;         // 4 warps over 128 N (32 each)
    const int m0 = blockIdx.x * BM;
    const int n0 = blockIdx.y * BN;

    const __half* Ag = g_X + (size_t)m0 * K;
    const __half* Bg = g_W + (size_t)n0 * K;

    float acc[4][4][4];
#pragma unroll
    for (int i = 0; i < 4; i++)
#pragma unroll
        for (int j = 0; j < 4; j++)
#pragma unroll
            for (int e = 0; e < 4; e++) acc[i][j][e] = 0.f;

    // ldmatrix address components (validated R2-R5):
    const int arow = wm * 64 + (lane & 15);
    const int asel = lane >> 4;                              // k-chunk +0/+1
    const int brow = wn * 32 + (((lane >> 4) & 1) << 3) + (lane & 7);
    const int bsel = (lane >> 3) & 1;

    // double-buffered fragments: A 2x16 regs, B 2x8 regs
    uint32_t afr[2][4][4], bfr[2][2][4];

    auto ldsm_frags = [&](uint32_t a_s, uint32_t b_s, int ks, int buf) {
        const int kc = ks * 2 + asel;
#pragma unroll
        for (int mf = 0; mf < 4; mf++) {
            int row = arow + mf * 16;
            ldsm4(afr[buf][mf], a_s + row * 128 + ((kc ^ (row & 7)) * 16));
        }
        const int kb = ks * 2 + bsel;
#pragma unroll
        for (int nf2 = 0; nf2 < 2; nf2++) {
            int row = brow + nf2 * 16;
            ldsm4(bfr[buf][nf2], b_s + row * 128 + ((kb ^ (row & 7)) * 16));
        }
    };

    // prologue: stages 0,1 in flight; stage 0 resident; preload ks=0 frags
    load_stage(sbase, 0, 0, Ag, Bg, tid);
    asm volatile("cp.async.commit_group;" ::: "memory");
    load_stage(sbase, 1, 1, Ag, Bg, tid);
    asm volatile("cp.async.commit_group;" ::: "memory");
    asm volatile("cp.async.wait_group 1;" ::: "memory");
    __syncthreads();
    ldsm_frags(sbase, sbase + A_BYTES, 0, 0);

    int slot = 0;
    for (int i = 0; i < NK; i++) {
        // issue fill for stage i+2 (overlaps with this stage's compute)
        if (i + 2 < NK) {
            int ns = slot - 1; if (ns < 0) ns += STAGES;     // (i+2) % 3
            load_stage(sbase, ns, i + 2, Ag, Bg, tid);
        }
        asm volatile("cp.async.commit_group;" ::: "memory");

        const uint32_t a_s = sbase + slot * STAGE_BYTES;
        const uint32_t b_s = a_s + A_BYTES;

#pragma unroll
        for (int ks = 0; ks < KC / 16; ks++) {
            const int cur = ks & 1;
            if (ks < KC / 16 - 1)
                ldsm_frags(a_s, b_s, ks + 1, cur ^ 1);   // prefetch next frags
#pragma unroll
            for (int mf = 0; mf < 4; mf++)
#pragma unroll
                for (int nf = 0; nf < 4; nf++)
                    mma16816(acc[mf][nf], afr[cur][mf],
                             &bfr[cur][nf >> 1][(nf & 1) * 2]);
        }

        slot++; if (slot == STAGES) slot = 0;

        // advance pipeline: stage i+1 resident, preload its ks=0 frags
        if (i + 1 < NK) {
            asm volatile("cp.async.wait_group 1;" ::: "memory");
            __syncthreads();   // all reads of the recycled slot are done above
            ldsm_frags(sbase + slot * STAGE_BYTES,
                       sbase + slot * STAGE_BYTES + A_BYTES, 0, 0);
        }
    }

    // Epilogue: register -> gmem float2 stores
    const int mbase = m0 + wm * 64 + (lane >> 2);
    const int nbase = n0 + wn * 32 + (lane & 3) * 2;
#pragma unroll
    for (int mf = 0; mf < 4; mf++)
#pragma unroll
        for (int nf = 0; nf < 4; nf++) {
            float* p0 = &out[(size_t)(mbase + mf * 16)     * N + nbase + nf * 8];
            float* p1 = &out[(size_t)(mbase + mf * 16 + 8) * N + nbase + nf * 8];
            *(float2*)p0 = make_float2(acc[mf][nf][0], acc[mf][nf][1]);
            *(float2*)p1 = make_float2(acc[mf][nf][2], acc[mf][nf][3]);
        }
}

// ----------------------------------------------------------------------------
extern "C" void kernel_launch(void* const* d_in, const int* in_sizes, int n_in,
                              void* d_out, int out_size) {
    (void)in_sizes; (void)n_in; (void)out_size;
    const float* x       = (const float*)d_in[0];
    const int*   qweight = (const int*)d_in[1];
    const float* scales  = (const float*)d_in[2];
    const int*   qzeros  = (const int*)d_in[3];
    float* out = (float*)d_out;

    prep_kernel<<<(XWORK + WWORK + 255) / 256, 256>>>(x, qweight, scales, qzeros);

    cudaFuncSetAttribute(gemm_kernel, cudaFuncAttributeMaxDynamicSharedMemorySize,
                         SMEM_BYTES);
    dim3 grid(M / BM, N / BN);   // (64, 86), m-fast: wave shares B via L2
    gemm_kernel<<<grid, THREADS, SMEM_BYTES>>>(out);
}

// round 7
// speedup vs baseline: 1.2880x; 1.2880x over previous
#include <cuda_runtime.h>
#include <cuda_fp16.h>
#include <cstdint>

// ============================================================================
// QuantLinear: out[M,N] = x[M,K] @ dequant(qweight, scales, qzeros)[K,N]
// M=8192, K=4096, N=11008, groupsize=128, 4-bit.
//
// compute_103 => mma.sync HMMA (rt=8, floor ~1.21ms). Best measured skeleton:
// 128x128x64 CTA, 256 thr, 8 warps 64x32, 2 CTAs/SM (R2, 1.58ms GEMM).
// This round: Marlin-style B — keep B as packed int4 in smem (4KB/stage vs
// 16KB), dequant at fragment level via fp16 magic numbers. Stage 20KB -> 4
// stages at 2 CTAs/SM, B LTS fill / 4, fewer live regs than R2.
//
// Prep: x fp32->fp16 g_X; repack qweight into lane-ordered words g_Wq;
//       pack {s, 1024+z} fp16 pairs g_SZ.
// ============================================================================

constexpr int M = 8192;
constexpr int N = 11008;
constexpr int K = 4096;

constexpr int BM = 128;
constexpr int BN = 128;
constexpr int KC = 64;
constexpr int STAGES = 4;
constexpr int NK = K / KC;         // 64
constexpr int THREADS = 256;
constexpr int NTILES = N / BN;     // 86

constexpr int A_BYTES = BM * 128;                 // 16384
constexpr int B_BYTES = BN * KC / 2;              // 4096 (int4)
constexpr int STAGE_BYTES = A_BYTES + B_BYTES;    // 20480
constexpr int SMEM_BYTES = STAGES * STAGE_BYTES;  // 81920 -> 2 CTAs/SM

constexpr int XWORK  = M * K / 4;                 // x convert items (float4)
constexpr int WQWORK = NTILES * NK * 1024;        // repacked words = (K/8)*N
constexpr int SZWORK = (K / 128) * N;             // 32 * 11008

static_assert(M % BM == 0 && N % BN == 0 && K % KC == 0, "exact tiling");

__device__ __half    g_X [(size_t)M * K];         // [M, K] fp16
__device__ unsigned  g_Wq[(size_t)WQWORK];        // repacked 4-bit B
__device__ unsigned  g_SZ[(size_t)SZWORK];        // {s:f16, 1024+z:f16}

// ----------------------------------------------------------------------------
// helpers
// ----------------------------------------------------------------------------
__device__ __forceinline__ void cp16(uint32_t smem_dst, const void* gsrc) {
    asm volatile("cp.async.cg.shared.global [%0], [%1], 16;"
                 :: "r"(smem_dst), "l"(gsrc));
}

__device__ __forceinline__ void ldsm4(uint32_t* r, uint32_t addr) {
    asm volatile("ldmatrix.sync.aligned.m8n8.x4.shared.b16 {%0,%1,%2,%3}, [%4];"
                 : "=r"(r[0]), "=r"(r[1]), "=r"(r[2]), "=r"(r[3]) : "r"(addr));
}

__device__ __forceinline__ uint32_t lds32(uint32_t addr) {
    uint32_t v;
    asm volatile("ld.shared.b32 %0, [%1];" : "=r"(v) : "r"(addr));
    return v;
}

__device__ __forceinline__ void mma16816(float* c, const uint32_t* a, const uint32_t* b) {
    asm volatile(
        "mma.sync.aligned.m16n8k16.row.col.f32.f16.f16.f32 "
        "{%0,%1,%2,%3}, {%4,%5,%6,%7}, {%8,%9}, {%0,%1,%2,%3};"
        : "+f"(c[0]), "+f"(c[1]), "+f"(c[2]), "+f"(c[3])
        : "r"(a[0]), "r"(a[1]), "r"(a[2]), "r"(a[3]), "r"(b[0]), "r"(b[1]));
}

// q>>sh has nibbles at bits[0:4) and [16:20) -> half2 of (1024+v); exact
// subtract of (1024+z), one fp16 rounding on multiply by s.
__device__ __forceinline__ uint32_t deq(uint32_t qsh, uint32_t hc2, uint32_t hs2) {
    uint32_t e = (qsh & 0x000F000Fu) | 0x64006400u;
    __half2 t = __hsub2(*(__half2*)&e, *(__half2*)&hc2);
    t = __hmul2(t, *(__half2*)&hs2);
    return *(uint32_t*)&t;
}

// ----------------------------------------------------------------------------
// Pass 1: fused prep (x convert | qweight repack | scale/zero pack)
//
// Repack word layout (word index within an n-tile = kt*1024 + ks*256 +
// wn*64 + w1*32 + l): n = tile*128 + wn*32 + w1*16 + (l>>2),
// k0 = kt*64 + ks*16 + (l&3)*2. Nibble slots (little-endian 0..7):
//   0:(n,k0) 1:(n,k0+8) 2:(n+8,k0) 3:(n+8,k0+8)
//   4:(n,k0+1) 5:(n,k0+9) 6:(n+8,k0+1) 7:(n+8,k0+9)
// so shifts 0/4/8/12 under mask 0x000F000F yield the 4 mma b-half2s.
// ----------------------------------------------------------------------------
__global__ void __launch_bounds__(256)
prep_kernel(const float* __restrict__ x, const int* __restrict__ qweight,
            const float* __restrict__ scales, const int* __restrict__ qzeros) {
    int idx = blockIdx.x * 256 + threadIdx.x;
    if (idx < XWORK) {
        float4 v = ((const float4*)x)[idx];
        __half2 h0 = __floats2half2_rn(v.x, v.y);
        __half2 h1 = __floats2half2_rn(v.z, v.w);
        uint2 o;
        o.x = *(unsigned*)&h0;
        o.y = *(unsigned*)&h1;
        ((uint2*)g_X)[idx] = o;
        return;
    }
    int widx = idx - XWORK;
    if (widx < WQWORK) {
        const unsigned* qw = (const unsigned*)qweight;
        int tile = widx >> 16;            // 65536 words per n-tile
        int rem  = widx & 65535;
        int kt = rem >> 10;
        int t  = rem & 1023;
        int l  = t & 31;
        int w1 = (t >> 5) & 1;
        int wn = (t >> 6) & 3;
        int ks = t >> 8;
        int n  = tile * 128 + wn * 32 + w1 * 16 + (l >> 2);
        int k0 = kt * 64 + ks * 16 + (l & 3) * 2;
        int row0 = k0 >> 3;               // k0,k0+1 in this qweight row
        int sh   = (k0 & 7) * 4;
        unsigned qa0 = qw[(size_t)row0 * N + n];
        unsigned qa1 = qw[(size_t)(row0 + 1) * N + n];
        unsigned qb0 = qw[(size_t)row0 * N + n + 8];
        unsigned qb1 = qw[(size_t)(row0 + 1) * N + n + 8];
        unsigned w =
              ((qa0 >> sh) & 0xF)
            | (((qa1 >> sh) & 0xF) << 4)
            | (((qb0 >> sh) & 0xF) << 8)
            | (((qb1 >> sh) & 0xF) << 12)
            | (((qa0 >> (sh + 4)) & 0xF) << 16)
            | (((qa1 >> (sh + 4)) & 0xF) << 20)
            | (((qb0 >> (sh + 4)) & 0xF) << 24)
            | (((qb1 >> (sh + 4)) & 0xF) << 28);
        g_Wq[widx] = w;
        return;
    }
    int sz = widx - WQWORK;
    if (sz >= SZWORK) return;
    int n = sz % N;
    int g = sz / N;
    float s = scales[(size_t)g * N + n];
    unsigned qz = ((const unsigned*)qzeros)[(size_t)g * (N / 8) + (n >> 3)];
    int z = (qz >> ((n & 7) * 4)) & 0xF;
    __half hs = __float2half(s);
    __half hc = __float2half((float)(1024 + z));   // exact
    g_SZ[sz] = (unsigned)*(unsigned short*)&hs
             | ((unsigned)*(unsigned short*)&hc << 16);
}

// ----------------------------------------------------------------------------
// Stage loader: A 128 rows x 128B (SW128, cp.async x4) + B 4KB contiguous.
// ----------------------------------------------------------------------------
__device__ __forceinline__ void load_stage(uint32_t sbase, int slot, int kt,
                                           const __half* Ag, const unsigned* Bq,
                                           int tid) {
    const uint32_t a_s = sbase + slot * STAGE_BYTES;
    const __half* Ak = Ag + kt * KC;
#pragma unroll
    for (int it = 0; it < 4; it++) {        // 128 rows * 8 chunks / 256 thr
        int idx = tid + it * THREADS;
        int r = idx >> 3, c = idx & 7;
        uint32_t off = (uint32_t)r * 128 + (uint32_t)((c ^ (r & 7)) * 16);
        cp16(a_s + off, Ak + (size_t)r * K + c * 8);
    }
    cp16(a_s + A_BYTES + tid * 16, Bq + (size_t)kt * 1024 + tid * 4);
}

// ----------------------------------------------------------------------------
// Pass 2: GEMM
// ----------------------------------------------------------------------------
__global__ void __launch_bounds__(THREADS, 2)
gemm_kernel(float* __restrict__ out) {
    extern __shared__ char smem[];
    const uint32_t sbase = (uint32_t)__cvta_generic_to_shared(smem);
    const int tid  = threadIdx.x;
    const int warp = tid >> 5;
    const int lane = tid & 31;
    const int wm = warp & 1;          // 2 warps over 128 M
    const int wn = warp >> 1;         // 4 warps over 128 N (32 each)
    const int m0 = blockIdx.x * BM;
    const int n0 = blockIdx.y * BN;

    const __half* Ag = g_X + (size_t)m0 * K;
    const unsigned* Bq = g_Wq + (size_t)blockIdx.y * 65536;

    float acc[4][4][4];
#pragma unroll
    for (int i = 0; i < 4; i++)
#pragma unroll
        for (int j = 0; j < 4; j++)
#pragma unroll
            for (int e = 0; e < 4; e++) acc[i][j][e] = 0.f;

    // A ldmatrix components (validated R2-R6)
    const int arow = wm * 64 + (lane & 15);
    const int asel = lane >> 4;
    // B lds geometry: lane word = ks*1024 + wn*256 + w1*128 + lane*4
    const uint32_t bword = wn * 256 + lane * 4;

    // per-group fp16 constants for this lane's 4 n values (n0+wn*32+j*8+(l>>2))
    uint32_t hs2c[4], hc2c[4];
    const unsigned* SZlane = g_SZ + n0 + wn * 32 + (lane >> 2);

    // prologue: stages 0..2 in flight
#pragma unroll
    for (int s = 0; s < STAGES - 1; s++) {
        load_stage(sbase, s, s, Ag, Bq, tid);
        asm volatile("cp.async.commit_group;" ::: "memory");
    }

    for (int i = 0; i < NK; i++) {
        const int slot = i & (STAGES - 1);
        asm volatile("cp.async.wait_group %0;" :: "n"(STAGES - 2) : "memory");
        __syncthreads();   // stage i resident; recycled slot fully consumed

        if ((i & 1) == 0) {                  // group changes every 2 stages
            const unsigned* SZg = SZlane + (size_t)(i >> 1) * N;
#pragma unroll
            for (int j = 0; j < 4; j++) {
                unsigned u = __ldg(&SZg[j * 8]);
                hs2c[j] = (u & 0xFFFFu) * 0x10001u;
                hc2c[j] = (u >> 16) * 0x10001u;
            }
        }

        if (i + STAGES - 1 < NK)
            load_stage(sbase, (i + STAGES - 1) & (STAGES - 1), i + STAGES - 1,
                       Ag, Bq, tid);
        asm volatile("cp.async.commit_group;" ::: "memory");

        const uint32_t a_s = sbase + slot * STAGE_BYTES;
        const uint32_t b_s = a_s + A_BYTES;

#pragma unroll
        for (int ks = 0; ks < KC / 16; ks++) {
            uint32_t a[4][4];
#pragma unroll
            for (int mf = 0; mf < 4; mf++) {
                int row = arow + mf * 16;
                int kc  = ks * 2 + asel;
                ldsm4(a[mf], a_s + row * 128 + ((kc ^ (row & 7)) * 16));
            }
            const uint32_t q0 = lds32(b_s + ks * 1024 + bword);
            const uint32_t q1 = lds32(b_s + ks * 1024 + bword + 128);
            uint32_t b0[2] = { deq(q0,       hc2c[0], hs2c[0]),
                               deq(q0 >> 4,  hc2c[0], hs2c[0]) };
            uint32_t b1[2] = { deq(q0 >> 8,  hc2c[1], hs2c[1]),
                               deq(q0 >> 12, hc2c[1], hs2c[1]) };
            uint32_t b2[2] = { deq(q1,       hc2c[2], hs2c[2]),
                               deq(q1 >> 4,  hc2c[2], hs2c[2]) };
            uint32_t b3[2] = { deq(q1 >> 8,  hc2c[3], hs2c[3]),
                               deq(q1 >> 12, hc2c[3], hs2c[3]) };
#pragma unroll
            for (int mf = 0; mf < 4; mf++) {
                mma16816(acc[mf][0], a[mf], b0);
                mma16816(acc[mf][1], a[mf], b1);
                mma16816(acc[mf][2], a[mf], b2);
                mma16816(acc[mf][3], a[mf], b3);
            }
        }
    }

    // Epilogue: register -> gmem float2 stores (verbatim R2)
    const int mbase = m0 + wm * 64 + (lane >> 2);
    const int nbase = n0 + wn * 32 + (lane & 3) * 2;
#pragma unroll
    for (int mf = 0; mf < 4; mf++)
#pragma unroll
        for (int nf = 0; nf < 4; nf++) {
            float* p0 = &out[(size_t)(mbase + mf * 16)     * N + nbase + nf * 8];
            float* p1 = &out[(size_t)(mbase + mf * 16 + 8) * N + nbase + nf * 8];
            *(float2*)p0 = make_float2(acc[mf][nf][0], acc[mf][nf][1]);
            *(float2*)p1 = make_float2(acc[mf][nf][2], acc[mf][nf][3]);
        }
}

// ----------------------------------------------------------------------------
extern "C" void kernel_launch(void* const* d_in, const int* in_sizes, int n_in,
                              void* d_out, int out_size) {
    (void)in_sizes; (void)n_in; (void)out_size;
    const float* x       = (const float*)d_in[0];
    const int*   qweight = (const int*)d_in[1];
    const float* scales  = (const float*)d_in[2];
    const int*   qzeros  = (const int*)d_in[3];
    float* out = (float*)d_out;

    prep_kernel<<<(XWORK + WQWORK + SZWORK + 255) / 256, 256>>>(
        x, qweight, scales, qzeros);

    cudaFuncSetAttribute(gemm_kernel, cudaFuncAttributeMaxDynamicSharedMemorySize,
                         SMEM_BYTES);
    dim3 grid(M / BM, N / BN);   // (64, 86), m-fast: B words shared via L2
    gemm_kernel<<<grid, THREADS, SMEM_BYTES>>>(out);
}

// round 8
// speedup vs baseline: 1.5427x; 1.1978x over previous
#include <cuda_runtime.h>
#include <cuda_fp16.h>
#include <cstdint>

// ============================================================================
// QuantLinear: out[M,N] = x[M,K] @ dequant(qweight, scales, qzeros)[K,N]
// M=8192, K=4096, N=11008, groupsize=128, 4-bit.
//
// compute_103 => mma.sync HMMA, rt_SMSP=8 (tensor-busy 1.21ms across R4/5/7).
// Best measured config (R2): CTA 128x128x64, 256 thr, 8 warps 64x32, 3-stage
// cp.async, 2 CTAs/SM, regs ~124. All attempted additions (fusion, bigger
// warp tiles, frag dbuf, in-loop dequant) regressed via regs/in-phase stalls.
//
// This round = R2 verbatim + (a) fused prep (validated), (b) next-stage fill
// issued AFTER the ks compute loop, shortening the post-barrier critical path.
// ============================================================================

constexpr int M = 8192;
constexpr int N = 11008;
constexpr int K = 4096;

constexpr int BM = 128;
constexpr int BN = 128;
constexpr int KC = 64;             // halves per stage = 128B rows (SW128)
constexpr int STAGES = 3;
constexpr int NK = K / KC;         // 64
constexpr int THREADS = 256;

constexpr int A_BYTES = BM * 128;                 // 16384
constexpr int STAGE_BYTES = 2 * A_BYTES;          // 32768 (A then B)
constexpr int SMEM_BYTES = STAGES * STAGE_BYTES;  // 98304 -> 2 CTAs/SM

constexpr int XWORK = M * K / 4;        // float4 items in convert part
constexpr int WWORK = (K / 8) * N;      // int32 items in dequant part

static_assert(M % BM == 0 && N % BN == 0 && K % KC == 0, "exact tiling");

__device__ __half g_X[(size_t)M * K];   // [M, K] fp16
__device__ __half g_W[(size_t)N * K];   // [N, K] fp16 (W^T), K-major

// ----------------------------------------------------------------------------
// helpers
// ----------------------------------------------------------------------------
__device__ __forceinline__ void cp16(uint32_t smem_dst, const void* gsrc) {
    asm volatile("cp.async.cg.shared.global [%0], [%1], 16;"
                 :: "r"(smem_dst), "l"(gsrc));
}

__device__ __forceinline__ void ldsm4(uint32_t* r, uint32_t addr) {
    asm volatile("ldmatrix.sync.aligned.m8n8.x4.shared.b16 {%0,%1,%2,%3}, [%4];"
                 : "=r"(r[0]), "=r"(r[1]), "=r"(r[2]), "=r"(r[3]) : "r"(addr));
}

__device__ __forceinline__ void mma16816(float* c, const uint32_t* a, const uint32_t* b) {
    asm volatile(
        "mma.sync.aligned.m16n8k16.row.col.f32.f16.f16.f32 "
        "{%0,%1,%2,%3}, {%4,%5,%6,%7}, {%8,%9}, {%0,%1,%2,%3};"
        : "+f"(c[0]), "+f"(c[1]), "+f"(c[2]), "+f"(c[3])
        : "r"(a[0]), "r"(a[1]), "r"(a[2]), "r"(a[3]), "r"(b[0]), "r"(b[1]));
}

// ----------------------------------------------------------------------------
// Pass 1: fused x-convert + dequant (validated R4/R5/R7)
// ----------------------------------------------------------------------------
__global__ void __launch_bounds__(256)
prep_kernel(const float* __restrict__ x, const int* __restrict__ qweight,
            const float* __restrict__ scales, const int* __restrict__ qzeros) {
    int idx = blockIdx.x * 256 + threadIdx.x;
    if (idx < XWORK) {
        float4 v = ((const float4*)x)[idx];
        __half2 h0 = __floats2half2_rn(v.x, v.y);
        __half2 h1 = __floats2half2_rn(v.z, v.w);
        uint2 o;
        o.x = *(unsigned*)&h0;
        o.y = *(unsigned*)&h1;
        ((uint2*)g_X)[idx] = o;
        return;
    }
    int widx = idx - XWORK;          // over (K/8)*N
    if (widx >= WWORK) return;
    int n = widx % N;
    int r = widx / N;
    int g = r >> 4;                  // groupsize 128 = 16 qweight rows
    unsigned q  = ((const unsigned*)qweight)[widx];
    unsigned qz = ((const unsigned*)qzeros)[g * (N / 8) + (n >> 3)];
    float z = (float)((qz >> ((n & 7) * 4)) & 0xF);
    float s = scales[g * N + n];
    __half2 outv[4];
#pragma unroll
    for (int j = 0; j < 4; j++) {
        float v0 = s * ((float)((q >> (8 * j))     & 0xF) - z);
        float v1 = s * ((float)((q >> (8 * j + 4)) & 0xF) - z);
        outv[j] = __floats2half2_rn(v0, v1);
    }
    *(uint4*)&g_W[(size_t)n * K + r * 8] = *(uint4*)outv;
}

// ----------------------------------------------------------------------------
// Stage loader (verbatim R2): A 128 rows + B 128 rows, 128B/row, SW128.
// Row r, 16B chunk c at r*128 + ((c ^ (r&7))*16).
// ----------------------------------------------------------------------------
__device__ __forceinline__ void load_stage(uint32_t sbase, int slot, int kt,
                                           const __half* Ag, const __half* Bg,
                                           int tid) {
    const uint32_t a_s = sbase + slot * STAGE_BYTES;
    const uint32_t b_s = a_s + A_BYTES;
    const __half* Ak = Ag + kt * KC;
    const __half* Bk = Bg + kt * KC;
#pragma unroll
    for (int it = 0; it < 4; it++) {        // 128 rows * 8 chunks / 256 thr
        int idx = tid + it * THREADS;
        int r = idx >> 3, c = idx & 7;
        uint32_t off = (uint32_t)r * 128 + (uint32_t)((c ^ (r & 7)) * 16);
        cp16(a_s + off, Ak + (size_t)r * K + c * 8);
        cp16(b_s + off, Bk + (size_t)r * K + c * 8);
    }
}

// ----------------------------------------------------------------------------
// Pass 2: GEMM (R2 skeleton; fill issued after compute)
// ----------------------------------------------------------------------------
__global__ void __launch_bounds__(THREADS, 2)
gemm_kernel(float* __restrict__ out) {
    extern __shared__ char smem[];
    const uint32_t sbase = (uint32_t)__cvta_generic_to_shared(smem);
    const int tid  = threadIdx.x;
    const int warp = tid >> 5;
    const int lane = tid & 31;
    const int wm = warp & 1;          // 2 warps over 128 M (64 each)
    const int wn = warp >> 1;         // 4 warps over 128 N (32 each)
    const int m0 = blockIdx.x * BM;
    const int n0 = blockIdx.y * BN;

    const __half* Ag = g_X + (size_t)m0 * K;
    const __half* Bg = g_W + (size_t)n0 * K;

    float acc[4][4][4];
#pragma unroll
    for (int i = 0; i < 4; i++)
#pragma unroll
        for (int j = 0; j < 4; j++)
#pragma unroll
            for (int e = 0; e < 4; e++) acc[i][j][e] = 0.f;

    // ldmatrix address components (validated R2-R7):
    const int arow = wm * 64 + (lane & 15);
    const int asel = lane >> 4;                              // k-chunk +0/+1
    const int brow = wn * 32 + (((lane >> 4) & 1) << 3) + (lane & 7);
    const int bsel = (lane >> 3) & 1;

    // prologue: fills for stages 0,1 in flight; stage 0 resident after sync
    load_stage(sbase, 0, 0, Ag, Bg, tid);
    asm volatile("cp.async.commit_group;" ::: "memory");
    load_stage(sbase, 1, 1, Ag, Bg, tid);
    asm volatile("cp.async.commit_group;" ::: "memory");
    asm volatile("cp.async.wait_group 1;" ::: "memory");
    __syncthreads();

    int slot = 0;
    for (int i = 0; i < NK; i++) {
        // stage i resident: compute first (no LDGSTS in front of first MMA)
        const uint32_t a_s = sbase + slot * STAGE_BYTES;
        const uint32_t b_s = a_s + A_BYTES;
#pragma unroll
        for (int ks = 0; ks < KC / 16; ks++) {
            uint32_t a[4][4], b[2][4];
#pragma unroll
            for (int mf = 0; mf < 4; mf++) {
                int row = arow + mf * 16;
                int kc  = ks * 2 + asel;
                ldsm4(a[mf], a_s + row * 128 + ((kc ^ (row & 7)) * 16));
            }
#pragma unroll
            for (int nf2 = 0; nf2 < 2; nf2++) {
                int row = brow + nf2 * 16;
                int kc  = ks * 2 + bsel;
                ldsm4(b[nf2], b_s + row * 128 + ((kc ^ (row & 7)) * 16));
            }
#pragma unroll
            for (int mf = 0; mf < 4; mf++)
#pragma unroll
                for (int nf = 0; nf < 4; nf++)
                    mma16816(acc[mf][nf], a[mf], &b[nf >> 1][(nf & 1) * 2]);
        }

        // issue fill for stage i+2 into slot (i+2)%3 = slot(i-1): all reads of
        // that slot finished before the barrier at the end of iter i-1.
        if (i + 2 < NK) {
            int ns = slot - 1; if (ns < 0) ns += STAGES;     // (i+2) % 3
            load_stage(sbase, ns, i + 2, Ag, Bg, tid);
        }
        asm volatile("cp.async.commit_group;" ::: "memory");

        slot++; if (slot == STAGES) slot = 0;

        // advance: <=1 group pending (the fill just issued) => stage i+1 landed
        if (i + 1 < NK) {
            asm volatile("cp.async.wait_group 1;" ::: "memory");
            __syncthreads();
        }
    }

    // Epilogue (verbatim R2): register -> gmem float2 stores
    const int mbase = m0 + wm * 64 + (lane >> 2);
    const int nbase = n0 + wn * 32 + (lane & 3) * 2;
#pragma unroll
    for (int mf = 0; mf < 4; mf++)
#pragma unroll
        for (int nf = 0; nf < 4; nf++) {
            float* p0 = &out[(size_t)(mbase + mf * 16)     * N + nbase + nf * 8];
            float* p1 = &out[(size_t)(mbase + mf * 16 + 8) * N + nbase + nf * 8];
            *(float2*)p0 = make_float2(acc[mf][nf][0], acc[mf][nf][1]);
            *(float2*)p1 = make_float2(acc[mf][nf][2], acc[mf][nf][3]);
        }
}

// ----------------------------------------------------------------------------
extern "C" void kernel_launch(void* const* d_in, const int* in_sizes, int n_in,
                              void* d_out, int out_size) {
    (void)in_sizes; (void)n_in; (void)out_size;
    const float* x       = (const float*)d_in[0];
    const int*   qweight = (const int*)d_in[1];
    const float* scales  = (const float*)d_in[2];
    const int*   qzeros  = (const int*)d_in[3];
    float* out = (float*)d_out;

    prep_kernel<<<(XWORK + WWORK + 255) / 256, 256>>>(x, qweight, scales, qzeros);

    cudaFuncSetAttribute(gemm_kernel, cudaFuncAttributeMaxDynamicSharedMemorySize,
                         SMEM_BYTES);
    dim3 grid(M / BM, N / BN);   // (64, 86), m-fast: wave shares B via L2
    gemm_kernel<<<grid, THREADS, SMEM_BYTES>>>(out);
}